// round 15
// baseline (speedup 1.0000x reference)
#include <cuda_runtime.h>
#include <cuda_fp16.h>
#include <cstdint>

// ---------------------------------------------------------------------------
// GCN_40037685134216: 4-layer GCN + mean-pool + MLP head, fp32.
// R15: fused gather+GEMM kernel per layer: gather writes relu'd fp16 rows
//      directly into the A smem tile; W cp.async'd at block start (hidden
//      behind gather); then R14's barrier-free ldmatrix+mma. Deletes the
//      Ax global round-trip between scatter and GEMM.
// ---------------------------------------------------------------------------

#define MAX_N 100000
#define MAX_E 1600000
#define DD    128
#define MAX_G 512
#define SCAN_BLK 1024
#define NB ((MAX_N + SCAN_BLK - 1) / SCAN_BLK)   // 98
#define WPAIRS (4 * DD * (DD/2))                  // 32768 packed fp16x2 words
#define APAIRS (MAX_N * (DD/2))                   // 6.4M words

__device__ __align__(16) int    g_cnt [MAX_N];
__device__ __align__(16) int    g_rowptr[MAX_N + 1];
__device__ __align__(16) int    g_cur [MAX_N];
__device__ __align__(16) int    g_eadj[MAX_E];
__device__ __align__(16) float  g_dinv[MAX_N];
__device__ __align__(16) int    g_bsum[NB];
__device__ __align__(16) int    g_boff[NB];
__device__ __align__(16) uint32_t g_Wh[WPAIRS];   // W fp16x2, [L][n][kpair]
__device__ __align__(16) uint32_t g_Ax[APAIRS];   // x as fp16x2 (layer-0 input)
__device__ __align__(16) __half2 g_yA[MAX_N * (DD/2)];
__device__ __align__(16) __half2 g_yB[MAX_N * (DD/2)];
__device__ float4 g_psum[MAX_G * (DD/4)];
__device__ float  g_pcnt[MAX_G];

// ---------------------------------------------------------------------------
// init pieces
// ---------------------------------------------------------------------------
__global__ void k_init(int* cnt, int N, const float* __restrict__ Ws,
                       uint32_t* __restrict__ Wh,
                       const float2* __restrict__ x2,
                       uint32_t* __restrict__ Ax, int apairs) {
    int i = blockIdx.x * blockDim.x + threadIdx.x;
    if (i < N) cnt[i] = 0;
    if (i < WPAIRS) {
        int L   = i >> 13;
        int rem = i & 8191;
        int n   = rem >> 6;
        int kp  = rem & 63;
        const float* W = Ws + (size_t)L * DD * DD;
        __half2 h = __floats2half2_rn(W[(2 * kp) * DD + n], W[(2 * kp + 1) * DD + n]);
        Wh[i] = *reinterpret_cast<uint32_t*>(&h);
    }
    if (i < apairs) {
        float2 v = x2[i];
        __half2 h = __floats2half2_rn(v.x, v.y);
        Ax[i] = *reinterpret_cast<uint32_t*>(&h);
    }
}

__global__ void k_count(const int* __restrict__ ei, int* cnt, int E) {
    int e = blockIdx.x * blockDim.x + threadIdx.x;
    if (e < E) atomicAdd(&cnt[ei[E + e]], 1);
}

__global__ void k_dinv(const int* __restrict__ cnt, float* dinv, int N) {
    int i = blockIdx.x * blockDim.x + threadIdx.x;
    if (i < N) dinv[i] = rsqrtf((float)cnt[i] + 1.0f);  // +1 self loop
}

__global__ __launch_bounds__(256)
void k_blocksum(const int* __restrict__ cnt, int* __restrict__ bsum, int N) {
    __shared__ int red[8];
    int b = blockIdx.x, t = threadIdx.x;
    int base = b * SCAN_BLK;
    int s = 0;
#pragma unroll
    for (int j = 0; j < 4; j++) {
        int i = base + t + j * 256;
        if (i < N) s += cnt[i];
    }
#pragma unroll
    for (int off = 16; off > 0; off >>= 1)
        s += __shfl_down_sync(0xffffffffu, s, off);
    if ((t & 31) == 0) red[t >> 5] = s;
    __syncthreads();
    if (t < 8) {
        s = red[t];
#pragma unroll
        for (int off = 4; off > 0; off >>= 1)
            s += __shfl_down_sync(0xffu, s, off);
        if (t == 0) bsum[b] = s;
    }
}

__global__ __launch_bounds__(128)
void k_scanbsum(const int* __restrict__ bsum, int* __restrict__ boff,
                int* __restrict__ rowptr, int nb, int N, int E) {
    __shared__ int s[128];
    int t = threadIdx.x;
    int v = (t < nb) ? bsum[t] : 0;
    s[t] = v;
    __syncthreads();
    for (int off = 1; off < 128; off <<= 1) {
        int u = (t >= off) ? s[t - off] : 0;
        __syncthreads();
        s[t] += u;
        __syncthreads();
    }
    if (t < nb) boff[t] = s[t] - v;
    if (t == 0) rowptr[N] = E;
}

__global__ __launch_bounds__(SCAN_BLK)
void k_scanblock(const int* __restrict__ cnt, const int* __restrict__ boff,
                 int* __restrict__ rowptr, int* __restrict__ cur, int N) {
    __shared__ int s[SCAN_BLK];
    int b = blockIdx.x, t = threadIdx.x;
    int i = b * SCAN_BLK + t;
    int v = (i < N) ? cnt[i] : 0;
    s[t] = v;
    __syncthreads();
    for (int off = 1; off < SCAN_BLK; off <<= 1) {
        int u = (t >= off) ? s[t - off] : 0;
        __syncthreads();
        s[t] += u;
        __syncthreads();
    }
    if (i < N) {
        int ex = boff[b] + s[t] - v;
        rowptr[i] = ex;
        cur[i]    = ex;
    }
}

__global__ void k_fill(const int* __restrict__ ei, int* cur,
                       int* __restrict__ eadj, int E) {
    int e = blockIdx.x * blockDim.x + threadIdx.x;
    if (e < E) {
        int r = ei[e];
        int c = ei[E + e];
        int pos = atomicAdd(&cur[c], 1);
        eadj[pos] = r;
    }
}

__global__ void k_zero_pool(float4* psum, float* pcnt, int G) {
    int t = blockIdx.x * blockDim.x + threadIdx.x;
    if (t < G * (DD/4)) psum[t] = make_float4(0.f, 0.f, 0.f, 0.f);
    if (t < G) pcnt[t] = 0.f;
}

// ---------------------------------------------------------------------------
// shared GEMM machinery
// ---------------------------------------------------------------------------
#define BM  128
#define PS  68                 // smem row pitch (words): conflict-free ldmatrix
#define SMW (128 * PS)
#define GEMM_SMEM (2 * SMW * 4)

__device__ __forceinline__ void mma_f16(float* c, const uint32_t* a, const uint32_t* b) {
    asm volatile("mma.sync.aligned.m16n8k16.row.col.f32.f16.f16.f32 "
                 "{%0,%1,%2,%3}, {%4,%5,%6,%7}, {%8,%9}, {%0,%1,%2,%3};"
                 : "+f"(c[0]), "+f"(c[1]), "+f"(c[2]), "+f"(c[3])
                 : "r"(a[0]), "r"(a[1]), "r"(a[2]), "r"(a[3]),
                   "r"(b[0]), "r"(b[1]));
}

__device__ __forceinline__ void ldm4(uint32_t* r, uint32_t addr) {
    asm volatile("ldmatrix.sync.aligned.m8n8.x4.shared.b16 {%0,%1,%2,%3}, [%4];"
                 : "=r"(r[0]), "=r"(r[1]), "=r"(r[2]), "=r"(r[3]) : "r"(addr));
}

__device__ __forceinline__ void cp16(uint32_t saddr, const void* g) {
    asm volatile("cp.async.cg.shared.global [%0], [%1], 16;"
                 :: "r"(saddr), "l"(g) : "memory");
}

__device__ __forceinline__ void acc_half4(float4& acc, uint2 raw) {
    __half2 h01 = *reinterpret_cast<__half2*>(&raw.x);
    __half2 h23 = *reinterpret_cast<__half2*>(&raw.y);
    float2 f01 = __half22float2(h01);
    float2 f23 = __half22float2(h23);
    acc.x += f01.x; acc.y += f01.y; acc.z += f23.x; acc.w += f23.y;
}

// mma phase shared by k_gemm_f16 / k_fused: A,W resident in smem.
__device__ __forceinline__ void gemm_mma_phase(
    const uint32_t saA, const uint32_t saW,
    __half2* __restrict__ Y2, const float* __restrict__ dinv,
    int m0, int M, int lane, int wm, int wn) {
    const int j   = lane & 7;
    const int sel = lane >> 3;
    const int arow0 = wm * 32 + j + 8 * (sel & 1);
    const int acol  = 4 * (sel >> 1);
    int wrow[4];
#pragma unroll
    for (int u = 0; u < 4; u++)
        wrow[u] = wn * 64 + u * 16 + j + 8 * (sel >> 1);
    const int wcol = 4 * (sel & 1);
    const int grp = lane >> 2;
    const int tig = lane & 3;

    float acc[2][8][4];
#pragma unroll
    for (int f = 0; f < 2; f++)
#pragma unroll
        for (int g = 0; g < 8; g++)
#pragma unroll
            for (int k = 0; k < 4; k++) acc[f][g][k] = 0.0f;

#pragma unroll
    for (int c = 0; c < 8; c++) {
        uint32_t a[2][4];
        ldm4(a[0], saA + (uint32_t)((arow0)      * PS + c * 8 + acol) * 4);
        ldm4(a[1], saA + (uint32_t)((arow0 + 16) * PS + c * 8 + acol) * 4);
        uint32_t b[4][4];
#pragma unroll
        for (int u = 0; u < 4; u++)
            ldm4(b[u], saW + (uint32_t)(wrow[u] * PS + c * 8 + wcol) * 4);
#pragma unroll
        for (int f = 0; f < 2; f++)
#pragma unroll
            for (int g = 0; g < 8; g++)
                mma_f16(acc[f][g], a[f], &b[g >> 1][(g & 1) * 2]);
    }

#pragma unroll
    for (int f = 0; f < 2; f++) {
        int r0 = m0 + wm * 32 + f * 16 + grp;
        int r1 = r0 + 8;
        float d0 = (r0 < M) ? dinv[r0] : 0.f;
        float d1 = (r1 < M) ? dinv[r1] : 0.f;
#pragma unroll
        for (int g = 0; g < 8; g++) {
            int cc = wn * 64 + g * 8 + tig * 2;
            if (r0 < M)
                Y2[(size_t)r0 * (DD/2) + (cc >> 1)] =
                    __floats2half2_rn(acc[f][g][0] * d0, acc[f][g][1] * d0);
            if (r1 < M)
                Y2[(size_t)r1 * (DD/2) + (cc >> 1)] =
                    __floats2half2_rn(acc[f][g][2] * d1, acc[f][g][3] * d1);
        }
    }
}

// ---------------------------------------------------------------------------
// Layer-0 GEMM: A from global fp16 plane (x), bulk cp.async (R14 form).
// ---------------------------------------------------------------------------
__global__ __launch_bounds__(256, 2)
void k_gemm_f16(const uint32_t* __restrict__ Ax, const uint32_t* __restrict__ Wh,
                __half2* __restrict__ Y2, const float* __restrict__ dinv, int M) {
    extern __shared__ uint32_t sm[];
    uint32_t* Asm = sm;
    uint32_t* Wsm = sm + SMW;

    const int tid  = threadIdx.x;
    const int lane = tid & 31;
    const int wid  = tid >> 5;
    const int m0   = blockIdx.x * BM;

    const uint32_t saA = (uint32_t)__cvta_generic_to_shared(Asm);
    const uint32_t saW = (uint32_t)__cvta_generic_to_shared(Wsm);

#pragma unroll
    for (int i = 0; i < 8; i++) {
        int q   = tid + i * 256;
        int row = q >> 4;
        int qq  = q & 15;
        uint32_t doff = (uint32_t)(row * PS + qq * 4) * 4;
        int arow = min(m0 + row, M - 1);
        cp16(saA + doff, Ax + (size_t)arow * 64 + qq * 4);
        cp16(saW + doff, Wh + (size_t)row * 64 + qq * 4);
    }
    asm volatile("cp.async.commit_group;" ::: "memory");
    asm volatile("cp.async.wait_group 0;" ::: "memory");
    __syncthreads();

    gemm_mma_phase(saA, saW, Y2, dinv, m0, M, lane, wid & 3, wid >> 2);
}

// ---------------------------------------------------------------------------
// Fused gather+GEMM: y_out = dinv * ( relu(b + dinv*gather(y_in)) @ W )
// Gather writes fp16 rows straight into the A smem tile.
// ---------------------------------------------------------------------------
__global__ __launch_bounds__(256, 2)
void k_fused(const uint2* __restrict__ y2,
             const int* __restrict__ rowptr, const int* __restrict__ eadj,
             const float* __restrict__ dinv, const float* __restrict__ bias,
             const uint32_t* __restrict__ Wh,
             __half2* __restrict__ yout, int N) {
    extern __shared__ uint32_t sm[];
    uint32_t* Asm = sm;
    uint32_t* Wsm = sm + SMW;

    const int tid  = threadIdx.x;
    const int lane = tid & 31;
    const int wid  = tid >> 5;
    const int m0   = blockIdx.x * BM;

    const uint32_t saA = (uint32_t)__cvta_generic_to_shared(Asm);
    const uint32_t saW = (uint32_t)__cvta_generic_to_shared(Wsm);

    // start W load (hidden behind gather)
#pragma unroll
    for (int i = 0; i < 8; i++) {
        int q   = tid + i * 256;
        int row = q >> 4;
        int qq  = q & 15;
        cp16(saW + (uint32_t)(row * PS + qq * 4) * 4, Wh + (size_t)row * 64 + qq * 4);
    }
    asm volatile("cp.async.commit_group;" ::: "memory");

    // gather phase: warp wid handles local rows wid*16 .. wid*16+15
    const float4 b = ((const float4*)bias)[lane];
    for (int i = 0; i < 16; i++) {
        int lrow = wid * 16 + i;
        int node = m0 + lrow;
        uint32_t h0 = 0, h1 = 0;
        if (node < N) {
            int beg = rowptr[node];
            int end = rowptr[node + 1];
            float4 acc = make_float4(0.f, 0.f, 0.f, 0.f);
            acc_half4(acc, y2[(size_t)node * 32 + lane]);   // self loop
            for (int base = beg; base < end; base += 32) {
                int n = min(32, end - base);
                int s = (base + lane < end) ? eadj[base + lane] : 0;
#pragma unroll 4
                for (int jj = 0; jj < n; jj++) {
                    int src = __shfl_sync(0xffffffffu, s, jj);
                    acc_half4(acc, y2[(size_t)src * 32 + lane]);
                }
            }
            float di = dinv[node];
            float ox = fmaxf(fmaf(acc.x, di, b.x), 0.f);
            float oy = fmaxf(fmaf(acc.y, di, b.y), 0.f);
            float oz = fmaxf(fmaf(acc.z, di, b.z), 0.f);
            float ow = fmaxf(fmaf(acc.w, di, b.w), 0.f);
            __half2 p0 = __floats2half2_rn(ox, oy);
            __half2 p1 = __floats2half2_rn(oz, ow);
            h0 = *reinterpret_cast<uint32_t*>(&p0);
            h1 = *reinterpret_cast<uint32_t*>(&p1);
        }
        Asm[lrow * PS + 2 * lane]     = h0;
        Asm[lrow * PS + 2 * lane + 1] = h1;
    }

    asm volatile("cp.async.wait_group 0;" ::: "memory");
    __syncthreads();

    gemm_mma_phase(saA, saW, yout, dinv, m0, N, lane, wid & 3, wid >> 2);
}

// ---------------------------------------------------------------------------
// Final gather + mean-pool accumulation (layer 3).
// ---------------------------------------------------------------------------
__device__ __forceinline__ void red_add_v4(float* addr, float4 v) {
    asm volatile("red.global.add.v4.f32 [%0], {%1, %2, %3, %4};"
                 :: "l"(addr), "f"(v.x), "f"(v.y), "f"(v.z), "f"(v.w)
                 : "memory");
}

__global__ __launch_bounds__(256)
void k_scatter_pool(const uint2* __restrict__ y2,
                    const int* __restrict__ rowptr,
                    const int* __restrict__ eadj,
                    const float* __restrict__ dinv,
                    const float* __restrict__ bias,
                    const int* __restrict__ batch,
                    float4* __restrict__ psum, float* __restrict__ pcnt,
                    int N) {
    int node = (blockIdx.x * blockDim.x + threadIdx.x) >> 5;
    int lane = threadIdx.x & 31;
    if (node >= N) return;

    int beg = rowptr[node];
    int end = rowptr[node + 1];

    float4 acc = make_float4(0.f, 0.f, 0.f, 0.f);
    acc_half4(acc, y2[(size_t)node * 32 + lane]);   // self loop
    for (int base = beg; base < end; base += 32) {
        int n = min(32, end - base);
        int s = (base + lane < end) ? eadj[base + lane] : 0;
#pragma unroll 4
        for (int j = 0; j < n; j++) {
            int src = __shfl_sync(0xffffffffu, s, j);
            acc_half4(acc, y2[(size_t)src * 32 + lane]);
        }
    }
    float di = dinv[node];
    const float4 b = ((const float4*)bias)[lane];
    float4 o;
    o.x = fmaf(acc.x, di, b.x);
    o.y = fmaf(acc.y, di, b.y);
    o.z = fmaf(acc.z, di, b.z);
    o.w = fmaf(acc.w, di, b.w);

    int g = batch[node];
    red_add_v4((float*)(psum + g * (DD/4) + lane), o);
    if (lane == 0) atomicAdd(&pcnt[g], 1.0f);
}

// ---------------------------------------------------------------------------
// MLP head
// ---------------------------------------------------------------------------
__global__ __launch_bounds__(128)
void k_mlp(const float4* __restrict__ psum, const float* __restrict__ pcnt,
           const float* __restrict__ w1, const float* __restrict__ b1,
           const float* __restrict__ w2, const float* __restrict__ b2,
           float* __restrict__ out, int H) {
    __shared__ float p[DD];
    __shared__ float hid[128];
    int g   = blockIdx.x;
    int tid = threadIdx.x;

    float cnt = fmaxf(pcnt[g], 1.0f);
    float inv = 1.0f / cnt;
    const float* ps = (const float*)(psum + g * (DD/4));
    p[tid] = ps[tid] * inv;
    __syncthreads();

    if (tid < H) {
        float s = b1[tid];
#pragma unroll 8
        for (int k = 0; k < DD; k++) s += p[k] * w1[k * H + tid];
        hid[tid] = fmaxf(s, 0.f);
    }
    __syncthreads();

    if (tid < 4) {
        float s = b2[tid];
        for (int j = 0; j < H; j++) s += hid[j] * w2[j * 4 + tid];
        out[g * 4 + tid] = s;
    }
}

// ---------------------------------------------------------------------------
// Launch. GEMM0 remains the 4th submission (ncu slot). CSR on s2 overlaps it.
// ---------------------------------------------------------------------------
extern "C" void kernel_launch(void* const* d_in, const int* in_sizes, int n_in,
                              void* d_out, int out_size) {
    const float* x     = (const float*)d_in[0];
    const float* Ws    = (const float*)d_in[1];
    const float* bs    = (const float*)d_in[2];
    const float* w1    = (const float*)d_in[3];
    const float* b1    = (const float*)d_in[4];
    const float* w2    = (const float*)d_in[5];
    const float* b2    = (const float*)d_in[6];
    const int*   ei    = (const int*)d_in[7];
    const int*   batch = (const int*)d_in[8];
    float*       out   = (float*)d_out;

    const int N = in_sizes[8];
    const int E = in_sizes[7] / 2;
    const int G = out_size / 4;
    const int H = in_sizes[4];

    int *cnt, *rowptr, *cur, *eadj, *bsum, *boff;
    float *dinv, *pcnt;
    uint32_t *Wh, *Ax;
    __half2 *yA, *yB;
    float4 *psum;
    cudaGetSymbolAddress((void**)&cnt,    g_cnt);
    cudaGetSymbolAddress((void**)&rowptr, g_rowptr);
    cudaGetSymbolAddress((void**)&cur,    g_cur);
    cudaGetSymbolAddress((void**)&eadj,   g_eadj);
    cudaGetSymbolAddress((void**)&bsum,   g_bsum);
    cudaGetSymbolAddress((void**)&boff,   g_boff);
    cudaGetSymbolAddress((void**)&dinv,   g_dinv);
    cudaGetSymbolAddress((void**)&Wh,     g_Wh);
    cudaGetSymbolAddress((void**)&Ax,     g_Ax);
    cudaGetSymbolAddress((void**)&yA,     g_yA);
    cudaGetSymbolAddress((void**)&yB,     g_yB);
    cudaGetSymbolAddress((void**)&psum,   g_psum);
    cudaGetSymbolAddress((void**)&pcnt,   g_pcnt);

    static cudaStream_t s2 = nullptr;
    static cudaEvent_t evD = nullptr, evC = nullptr;
    static bool attrSet = false;
    if (!s2) {
        cudaStreamCreateWithFlags(&s2, cudaStreamNonBlocking);
        cudaEventCreateWithFlags(&evD, cudaEventDisableTiming);
        cudaEventCreateWithFlags(&evC, cudaEventDisableTiming);
    }
    if (!attrSet) {
        cudaFuncSetAttribute(k_gemm_f16,
                             cudaFuncAttributeMaxDynamicSharedMemorySize, GEMM_SMEM);
        cudaFuncSetAttribute(k_fused,
                             cudaFuncAttributeMaxDynamicSharedMemorySize, GEMM_SMEM);
        attrSet = true;
    }

    const int T  = 256;
    const int nb = (N + SCAN_BLK - 1) / SCAN_BLK;
    const int gemmBlocks = (N + BM - 1) / BM;
    const int nodeWarpBlocks = (N + 7) / 8;
    const int apairs = N * (DD/2);

    // init (stream0), then count->dinv on s2
    k_init <<<(apairs + T - 1) / T, T>>>(cnt, N, Ws, Wh, (const float2*)x, Ax, apairs);
    cudaEventRecord(evC, 0);
    cudaStreamWaitEvent(s2, evC, 0);
    k_count<<<(E + T - 1) / T, T, 0, s2>>>(ei, cnt, E);
    k_dinv <<<(N + T - 1) / T, T, 0, s2>>>(cnt, dinv, N);
    cudaEventRecord(evD, s2);

    // 4th submission: layer-0 GEMM (ncu capture slot)
    cudaStreamWaitEvent(0, evD, 0);
    k_gemm_f16<<<gemmBlocks, 256, GEMM_SMEM>>>(Ax, Wh, yA, dinv, N);

    // CSR build on s2, overlapping GEMM0
    k_blocksum <<<nb, 256, 0, s2>>>(cnt, bsum, N);
    k_scanbsum <<<1, 128, 0, s2>>>(bsum, boff, rowptr, nb, N, E);
    k_scanblock<<<nb, SCAN_BLK, 0, s2>>>(cnt, boff, rowptr, cur, N);
    k_fill     <<<(E + T - 1) / T, T, 0, s2>>>(ei, cur, eadj, E);
    k_zero_pool<<<(G * (DD/4) + T - 1) / T, T, 0, s2>>>(psum, pcnt, G);
    cudaEventRecord(evC, s2);
    cudaStreamWaitEvent(0, evC, 0);

    // fused layers: y_{L+1} = dinv * ( relu(b_L + dinv*gather(y_L)) @ W_{L+1} )
    k_fused<<<gemmBlocks, 256, GEMM_SMEM>>>((const uint2*)yA, rowptr, eadj, dinv,
                                            bs + 0 * DD, Wh + (size_t)1 * 8192, yB, N);
    k_fused<<<gemmBlocks, 256, GEMM_SMEM>>>((const uint2*)yB, rowptr, eadj, dinv,
                                            bs + 1 * DD, Wh + (size_t)2 * 8192, yA, N);
    k_fused<<<gemmBlocks, 256, GEMM_SMEM>>>((const uint2*)yA, rowptr, eadj, dinv,
                                            bs + 2 * DD, Wh + (size_t)3 * 8192, yB, N);

    // final gather + pool, then MLP
    k_scatter_pool<<<nodeWarpBlocks, 256>>>((const uint2*)yB, rowptr, eadj, dinv,
                                            bs + 3 * DD, batch, psum, pcnt, N);
    k_mlp<<<G, 128>>>(psum, pcnt, w1, b1, w2, b2, out, H);
}

// round 16
// speedup vs baseline: 1.5423x; 1.5423x over previous
#include <cuda_runtime.h>
#include <cuda_fp16.h>
#include <cstdint>

// ---------------------------------------------------------------------------
// GCN_40037685134216: 4-layer GCN + mean-pool + MLP head, fp32.
// R16: R14 kernels (proven), plus scatter/GEMM half-pipelining: the GEMM for
//      node-half 0 runs on stream s2 while the scatter for half 1 still runs
//      on stream 0. y double-buffered (yA/yB) to avoid read/write races.
// ---------------------------------------------------------------------------

#define MAX_N 100000
#define MAX_E 1600000
#define DD    128
#define MAX_G 512
#define SCAN_BLK 1024
#define NB ((MAX_N + SCAN_BLK - 1) / SCAN_BLK)   // 98
#define WPAIRS (4 * DD * (DD/2))                  // 32768 packed fp16x2 words
#define APAIRS (MAX_N * (DD/2))                   // 6.4M words

__device__ __align__(16) int    g_cnt [MAX_N];
__device__ __align__(16) int    g_rowptr[MAX_N + 1];
__device__ __align__(16) int    g_cur [MAX_N];
__device__ __align__(16) int    g_eadj[MAX_E];
__device__ __align__(16) float  g_dinv[MAX_N];
__device__ __align__(16) int    g_bsum[NB];
__device__ __align__(16) int    g_boff[NB];
__device__ __align__(16) uint32_t g_Wh[WPAIRS];   // W fp16x2, [L][n][kpair]
__device__ __align__(16) uint32_t g_Ax[APAIRS];   // fp16x2 A plane
__device__ __align__(16) __half2 g_yA[MAX_N * (DD/2)];
__device__ __align__(16) __half2 g_yB[MAX_N * (DD/2)];
__device__ float4 g_psum[MAX_G * (DD/4)];
__device__ float  g_pcnt[MAX_G];

// ---------------------------------------------------------------------------
// init pieces
// ---------------------------------------------------------------------------
__global__ void k_init(int* cnt, int N, const float* __restrict__ Ws,
                       uint32_t* __restrict__ Wh,
                       const float2* __restrict__ x2,
                       uint32_t* __restrict__ Ax, int apairs) {
    int i = blockIdx.x * blockDim.x + threadIdx.x;
    if (i < N) cnt[i] = 0;
    if (i < WPAIRS) {
        int L   = i >> 13;
        int rem = i & 8191;
        int n   = rem >> 6;
        int kp  = rem & 63;
        const float* W = Ws + (size_t)L * DD * DD;
        __half2 h = __floats2half2_rn(W[(2 * kp) * DD + n], W[(2 * kp + 1) * DD + n]);
        Wh[i] = *reinterpret_cast<uint32_t*>(&h);
    }
    if (i < apairs) {
        float2 v = x2[i];
        __half2 h = __floats2half2_rn(v.x, v.y);
        Ax[i] = *reinterpret_cast<uint32_t*>(&h);
    }
}

__global__ void k_count(const int* __restrict__ ei, int* cnt, int E) {
    int e = blockIdx.x * blockDim.x + threadIdx.x;
    if (e < E) atomicAdd(&cnt[ei[E + e]], 1);
}

__global__ void k_dinv(const int* __restrict__ cnt, float* dinv, int N) {
    int i = blockIdx.x * blockDim.x + threadIdx.x;
    if (i < N) dinv[i] = rsqrtf((float)cnt[i] + 1.0f);  // +1 self loop
}

__global__ __launch_bounds__(256)
void k_blocksum(const int* __restrict__ cnt, int* __restrict__ bsum, int N) {
    __shared__ int red[8];
    int b = blockIdx.x, t = threadIdx.x;
    int base = b * SCAN_BLK;
    int s = 0;
#pragma unroll
    for (int j = 0; j < 4; j++) {
        int i = base + t + j * 256;
        if (i < N) s += cnt[i];
    }
#pragma unroll
    for (int off = 16; off > 0; off >>= 1)
        s += __shfl_down_sync(0xffffffffu, s, off);
    if ((t & 31) == 0) red[t >> 5] = s;
    __syncthreads();
    if (t < 8) {
        s = red[t];
#pragma unroll
        for (int off = 4; off > 0; off >>= 1)
            s += __shfl_down_sync(0xffu, s, off);
        if (t == 0) bsum[b] = s;
    }
}

__global__ __launch_bounds__(128)
void k_scanbsum(const int* __restrict__ bsum, int* __restrict__ boff,
                int* __restrict__ rowptr, int nb, int N, int E) {
    __shared__ int s[128];
    int t = threadIdx.x;
    int v = (t < nb) ? bsum[t] : 0;
    s[t] = v;
    __syncthreads();
    for (int off = 1; off < 128; off <<= 1) {
        int u = (t >= off) ? s[t - off] : 0;
        __syncthreads();
        s[t] += u;
        __syncthreads();
    }
    if (t < nb) boff[t] = s[t] - v;
    if (t == 0) rowptr[N] = E;
}

__global__ __launch_bounds__(SCAN_BLK)
void k_scanblock(const int* __restrict__ cnt, const int* __restrict__ boff,
                 int* __restrict__ rowptr, int* __restrict__ cur, int N) {
    __shared__ int s[SCAN_BLK];
    int b = blockIdx.x, t = threadIdx.x;
    int i = b * SCAN_BLK + t;
    int v = (i < N) ? cnt[i] : 0;
    s[t] = v;
    __syncthreads();
    for (int off = 1; off < SCAN_BLK; off <<= 1) {
        int u = (t >= off) ? s[t - off] : 0;
        __syncthreads();
        s[t] += u;
        __syncthreads();
    }
    if (i < N) {
        int ex = boff[b] + s[t] - v;
        rowptr[i] = ex;
        cur[i]    = ex;
    }
}

__global__ void k_fill(const int* __restrict__ ei, int* cur,
                       int* __restrict__ eadj, int E) {
    int e = blockIdx.x * blockDim.x + threadIdx.x;
    if (e < E) {
        int r = ei[e];
        int c = ei[E + e];
        int pos = atomicAdd(&cur[c], 1);
        eadj[pos] = r;
    }
}

__global__ void k_zero_pool(float4* psum, float* pcnt, int G) {
    int t = blockIdx.x * blockDim.x + threadIdx.x;
    if (t < G * (DD/4)) psum[t] = make_float4(0.f, 0.f, 0.f, 0.f);
    if (t < G) pcnt[t] = 0.f;
}

// ---------------------------------------------------------------------------
// fp16 tensor-core GEMM (R14 form): whole A-tile + W resident in smem.
// mBase selects the node half.
// ---------------------------------------------------------------------------
#define BM  128
#define PS  68
#define SMW (128 * PS)
#define GEMM_SMEM (2 * SMW * 4)

__device__ __forceinline__ void mma_f16(float* c, const uint32_t* a, const uint32_t* b) {
    asm volatile("mma.sync.aligned.m16n8k16.row.col.f32.f16.f16.f32 "
                 "{%0,%1,%2,%3}, {%4,%5,%6,%7}, {%8,%9}, {%0,%1,%2,%3};"
                 : "+f"(c[0]), "+f"(c[1]), "+f"(c[2]), "+f"(c[3])
                 : "r"(a[0]), "r"(a[1]), "r"(a[2]), "r"(a[3]),
                   "r"(b[0]), "r"(b[1]));
}

__device__ __forceinline__ void ldm4(uint32_t* r, uint32_t addr) {
    asm volatile("ldmatrix.sync.aligned.m8n8.x4.shared.b16 {%0,%1,%2,%3}, [%4];"
                 : "=r"(r[0]), "=r"(r[1]), "=r"(r[2]), "=r"(r[3]) : "r"(addr));
}

__device__ __forceinline__ void cp16(uint32_t saddr, const void* g) {
    asm volatile("cp.async.cg.shared.global [%0], [%1], 16;"
                 :: "r"(saddr), "l"(g) : "memory");
}

__global__ __launch_bounds__(256, 2)
void k_gemm_f16(const uint32_t* __restrict__ Ax, const uint32_t* __restrict__ Wh,
                __half2* __restrict__ Y2, const float* __restrict__ dinv,
                int M, int mBase) {
    extern __shared__ uint32_t sm[];
    uint32_t* Asm = sm;
    uint32_t* Wsm = sm + SMW;

    const int tid  = threadIdx.x;
    const int lane = tid & 31;
    const int wid  = tid >> 5;
    const int wm   = wid & 3;
    const int wn   = wid >> 2;
    const int grp  = lane >> 2;
    const int tig  = lane & 3;
    const int m0   = mBase + blockIdx.x * BM;

    const uint32_t saA = (uint32_t)__cvta_generic_to_shared(Asm);
    const uint32_t saW = (uint32_t)__cvta_generic_to_shared(Wsm);

#pragma unroll
    for (int i = 0; i < 8; i++) {
        int q   = tid + i * 256;
        int row = q >> 4;
        int qq  = q & 15;
        uint32_t doff = (uint32_t)(row * PS + qq * 4) * 4;
        int arow = min(m0 + row, M - 1);
        cp16(saA + doff, Ax + (size_t)arow * 64 + qq * 4);
        cp16(saW + doff, Wh + (size_t)row * 64 + qq * 4);
    }
    asm volatile("cp.async.commit_group;" ::: "memory");
    asm volatile("cp.async.wait_group 0;" ::: "memory");
    __syncthreads();

    const int j   = lane & 7;
    const int sel = lane >> 3;
    const int arow0 = wm * 32 + j + 8 * (sel & 1);
    const int acol  = 4 * (sel >> 1);
    int wrow[4];
#pragma unroll
    for (int u = 0; u < 4; u++)
        wrow[u] = wn * 64 + u * 16 + j + 8 * (sel >> 1);
    const int wcol = 4 * (sel & 1);

    float acc[2][8][4];
#pragma unroll
    for (int f = 0; f < 2; f++)
#pragma unroll
        for (int g = 0; g < 8; g++)
#pragma unroll
            for (int k = 0; k < 4; k++) acc[f][g][k] = 0.0f;

#pragma unroll
    for (int c = 0; c < 8; c++) {
        uint32_t a[2][4];
        ldm4(a[0], saA + (uint32_t)((arow0)      * PS + c * 8 + acol) * 4);
        ldm4(a[1], saA + (uint32_t)((arow0 + 16) * PS + c * 8 + acol) * 4);
        uint32_t b[4][4];
#pragma unroll
        for (int u = 0; u < 4; u++)
            ldm4(b[u], saW + (uint32_t)(wrow[u] * PS + c * 8 + wcol) * 4);

#pragma unroll
        for (int f = 0; f < 2; f++)
#pragma unroll
            for (int g = 0; g < 8; g++)
                mma_f16(acc[f][g], a[f], &b[g >> 1][(g & 1) * 2]);
    }

#pragma unroll
    for (int f = 0; f < 2; f++) {
        int r0 = m0 + wm * 32 + f * 16 + grp;
        int r1 = r0 + 8;
        float d0 = (r0 < M) ? dinv[r0] : 0.f;
        float d1 = (r1 < M) ? dinv[r1] : 0.f;
#pragma unroll
        for (int g = 0; g < 8; g++) {
            int cc = wn * 64 + g * 8 + tig * 2;
            if (r0 < M)
                Y2[(size_t)r0 * (DD/2) + (cc >> 1)] =
                    __floats2half2_rn(acc[f][g][0] * d0, acc[f][g][1] * d0);
            if (r1 < M)
                Y2[(size_t)r1 * (DD/2) + (cc >> 1)] =
                    __floats2half2_rn(acc[f][g][2] * d1, acc[f][g][3] * d1);
        }
    }
}

// ---------------------------------------------------------------------------
// CSR scatter (R11/R13/R14 proven form), node range [nodeBeg, nodeEnd).
// ---------------------------------------------------------------------------
__device__ __forceinline__ void red_add_v4(float* addr, float4 v) {
    asm volatile("red.global.add.v4.f32 [%0], {%1, %2, %3, %4};"
                 :: "l"(addr), "f"(v.x), "f"(v.y), "f"(v.z), "f"(v.w)
                 : "memory");
}

__device__ __forceinline__ void acc_half4(float4& acc, uint2 raw) {
    __half2 h01 = *reinterpret_cast<__half2*>(&raw.x);
    __half2 h23 = *reinterpret_cast<__half2*>(&raw.y);
    float2 f01 = __half22float2(h01);
    float2 f23 = __half22float2(h23);
    acc.x += f01.x; acc.y += f01.y; acc.z += f23.x; acc.w += f23.y;
}

__global__ __launch_bounds__(256)
void k_scatter_csr(const uint2* __restrict__ y2,
                   const int* __restrict__ rowptr,
                   const int* __restrict__ eadj,
                   const float* __restrict__ dinv,
                   const float* __restrict__ bias,
                   uint2* __restrict__ Aout,        // non-pool output (fp16)
                   const int* __restrict__ batch,   // non-null => pool mode
                   float4* __restrict__ psum, float* __restrict__ pcnt,
                   int nodeBeg, int nodeEnd) {
    int node = nodeBeg + ((blockIdx.x * blockDim.x + threadIdx.x) >> 5);
    int lane = threadIdx.x & 31;
    if (node >= nodeEnd) return;

    int beg = rowptr[node];
    int end = rowptr[node + 1];

    float4 acc = make_float4(0.f, 0.f, 0.f, 0.f);
    acc_half4(acc, y2[(size_t)node * 32 + lane]);   // self loop
    for (int base = beg; base < end; base += 32) {
        int n = min(32, end - base);
        int s = (base + lane < end) ? eadj[base + lane] : 0;
#pragma unroll 4
        for (int j = 0; j < n; j++) {
            int src = __shfl_sync(0xffffffffu, s, j);
            acc_half4(acc, y2[(size_t)src * 32 + lane]);
        }
    }
    float di = dinv[node];
    const float4 b = ((const float4*)bias)[lane];
    float4 o;
    o.x = fmaf(acc.x, di, b.x);
    o.y = fmaf(acc.y, di, b.y);
    o.z = fmaf(acc.z, di, b.z);
    o.w = fmaf(acc.w, di, b.w);

    if (batch) {
        int g = batch[node];
        red_add_v4((float*)(psum + g * (DD/4) + lane), o);
        if (lane == 0) atomicAdd(&pcnt[g], 1.0f);
    } else {
        __half2 h0 = __floats2half2_rn(fmaxf(o.x, 0.f), fmaxf(o.y, 0.f));
        __half2 h1 = __floats2half2_rn(fmaxf(o.z, 0.f), fmaxf(o.w, 0.f));
        Aout[(size_t)node * 32 + lane] =
            make_uint2(*reinterpret_cast<uint32_t*>(&h0),
                       *reinterpret_cast<uint32_t*>(&h1));
    }
}

// ---------------------------------------------------------------------------
// MLP head
// ---------------------------------------------------------------------------
__global__ __launch_bounds__(128)
void k_mlp(const float4* __restrict__ psum, const float* __restrict__ pcnt,
           const float* __restrict__ w1, const float* __restrict__ b1,
           const float* __restrict__ w2, const float* __restrict__ b2,
           float* __restrict__ out, int H) {
    __shared__ float p[DD];
    __shared__ float hid[128];
    int g   = blockIdx.x;
    int tid = threadIdx.x;

    float cnt = fmaxf(pcnt[g], 1.0f);
    float inv = 1.0f / cnt;
    const float* ps = (const float*)(psum + g * (DD/4));
    p[tid] = ps[tid] * inv;
    __syncthreads();

    if (tid < H) {
        float s = b1[tid];
#pragma unroll 8
        for (int k = 0; k < DD; k++) s += p[k] * w1[k * H + tid];
        hid[tid] = fmaxf(s, 0.f);
    }
    __syncthreads();

    if (tid < 4) {
        float s = b2[tid];
        for (int j = 0; j < H; j++) s += hid[j] * w2[j * 4 + tid];
        out[g * 4 + tid] = s;
    }
}

// ---------------------------------------------------------------------------
// Launch. GEMM0 is the 4th kernel launch (ncu slot). Per layer, scatter h0 ->
// gemm h0 (s2) overlaps scatter h1 (stream 0); y double-buffered.
// ---------------------------------------------------------------------------
extern "C" void kernel_launch(void* const* d_in, const int* in_sizes, int n_in,
                              void* d_out, int out_size) {
    const float* x     = (const float*)d_in[0];
    const float* Ws    = (const float*)d_in[1];
    const float* bs    = (const float*)d_in[2];
    const float* w1    = (const float*)d_in[3];
    const float* b1    = (const float*)d_in[4];
    const float* w2    = (const float*)d_in[5];
    const float* b2    = (const float*)d_in[6];
    const int*   ei    = (const int*)d_in[7];
    const int*   batch = (const int*)d_in[8];
    float*       out   = (float*)d_out;

    const int N = in_sizes[8];
    const int E = in_sizes[7] / 2;
    const int G = out_size / 4;
    const int H = in_sizes[4];

    int *cnt, *rowptr, *cur, *eadj, *bsum, *boff;
    float *dinv, *pcnt;
    uint32_t *Wh, *Ax;
    __half2 *yA, *yB;
    float4 *psum;
    cudaGetSymbolAddress((void**)&cnt,    g_cnt);
    cudaGetSymbolAddress((void**)&rowptr, g_rowptr);
    cudaGetSymbolAddress((void**)&cur,    g_cur);
    cudaGetSymbolAddress((void**)&eadj,   g_eadj);
    cudaGetSymbolAddress((void**)&bsum,   g_bsum);
    cudaGetSymbolAddress((void**)&boff,   g_boff);
    cudaGetSymbolAddress((void**)&dinv,   g_dinv);
    cudaGetSymbolAddress((void**)&Wh,     g_Wh);
    cudaGetSymbolAddress((void**)&Ax,     g_Ax);
    cudaGetSymbolAddress((void**)&yA,     g_yA);
    cudaGetSymbolAddress((void**)&yB,     g_yB);
    cudaGetSymbolAddress((void**)&psum,   g_psum);
    cudaGetSymbolAddress((void**)&pcnt,   g_pcnt);

    static cudaStream_t s2 = nullptr;
    static cudaEvent_t ev[16];
    static bool inited = false;
    if (!inited) {
        cudaStreamCreateWithFlags(&s2, cudaStreamNonBlocking);
        for (int i = 0; i < 16; i++)
            cudaEventCreateWithFlags(&ev[i], cudaEventDisableTiming);
        cudaFuncSetAttribute(k_gemm_f16,
                             cudaFuncAttributeMaxDynamicSharedMemorySize, GEMM_SMEM);
        inited = true;
    }

    const int T  = 256;
    const int nb = (N + SCAN_BLK - 1) / SCAN_BLK;
    const int gemmBlocks = (N + BM - 1) / BM;
    const int apairs = N * (DD/2);

    // node halves (h0 boundary multiple of BM)
    const int NH0 = ((N / 2 + BM - 1) / BM) * BM;      // 50048
    const int gemmB0 = NH0 / BM;                        // 391
    const int gemmB1 = (N - NH0 + BM - 1) / BM;         // 391
    const int scatB0 = (NH0 + 7) / 8;
    const int scatB1 = (N - NH0 + 7) / 8;
    const int scatAll = (N + 7) / 8;

    int e = 0;  // event cursor

    // init (stream0), count->dinv (s2)
    k_init <<<(apairs + T - 1) / T, T>>>(cnt, N, Ws, Wh, (const float2*)x, Ax, apairs);
    cudaEventRecord(ev[e], 0);
    cudaStreamWaitEvent(s2, ev[e], 0); e++;
    k_count<<<(E + T - 1) / T, T, 0, s2>>>(ei, cnt, E);
    k_dinv <<<(N + T - 1) / T, T, 0, s2>>>(cnt, dinv, N);
    cudaEventRecord(ev[e], s2);
    cudaStreamWaitEvent(0, ev[e], 0); e++;

    // 4th launch: layer-0 GEMM full (ncu capture slot), overlapped with CSR on s2
    k_gemm_f16<<<gemmBlocks, 256, GEMM_SMEM, 0>>>(Ax, Wh, yA, dinv, N, 0);

    k_blocksum <<<nb, 256, 0, s2>>>(cnt, bsum, N);
    k_scanbsum <<<1, 128, 0, s2>>>(bsum, boff, rowptr, nb, N, E);
    k_scanblock<<<nb, SCAN_BLK, 0, s2>>>(cnt, boff, rowptr, cur, N);
    k_fill     <<<(E + T - 1) / T, T, 0, s2>>>(ei, cur, eadj, E);
    k_zero_pool<<<(G * (DD/4) + T - 1) / T, T, 0, s2>>>(psum, pcnt, G);
    cudaEventRecord(ev[e], s2);
    cudaStreamWaitEvent(0, ev[e], 0); e++;

    // layers 0..2: scatter(y_in -> Ax) half-pipelined with gemm(Ax -> y_out)
    __half2* yin  = yA;
    __half2* yout = yB;
    for (int L = 0; L < 3; L++) {
        // scatter half 0 (stream 0)
        k_scatter_csr<<<scatB0, 256, 0, 0>>>((const uint2*)yin, rowptr, eadj, dinv,
                                             bs + L * DD, (uint2*)Ax,
                                             nullptr, nullptr, nullptr, 0, NH0);
        cudaEventRecord(ev[e], 0);
        cudaStreamWaitEvent(s2, ev[e], 0); e++;
        // scatter half 1 (stream 0) -- overlaps gemm half 0 on s2
        k_scatter_csr<<<scatB1, 256, 0, 0>>>((const uint2*)yin, rowptr, eadj, dinv,
                                             bs + L * DD, (uint2*)Ax,
                                             nullptr, nullptr, nullptr, NH0, N);
        cudaEventRecord(ev[e], 0);
        // gemm half 0 on s2
        k_gemm_f16<<<gemmB0, 256, GEMM_SMEM, s2>>>(Ax, Wh + (size_t)(L + 1) * 8192,
                                                   yout, dinv, N, 0);
        cudaStreamWaitEvent(s2, ev[e], 0); e++;
        // gemm half 1 on s2
        k_gemm_f16<<<gemmB1, 256, GEMM_SMEM, s2>>>(Ax, Wh + (size_t)(L + 1) * 8192,
                                                   yout, dinv, N, NH0);
        cudaEventRecord(ev[e], s2);
        cudaStreamWaitEvent(0, ev[e], 0); e++;
        // swap buffers
        __half2* t = yin; yin = yout; yout = t;
    }

    // final gather + mean-pool (bias 3), then MLP
    k_scatter_csr<<<scatAll, 256, 0, 0>>>((const uint2*)yin, rowptr, eadj, dinv,
                                          bs + 3 * DD, nullptr,
                                          batch, psum, pcnt, 0, N);
    k_mlp<<<G, 128>>>(psum, pcnt, w1, b1, w2, b2, out, H);
}